// round 1
// baseline (speedup 1.0000x reference)
#include <cuda_runtime.h>
#include <cuda_bf16.h>

// Winograd F(4x4,3x3): N=16, Cin=Cout=64, H=W=128, pad=1, nt=32, T=16384.
// Weight arrives already transformed to 6x6 domain.
//
// Pipeline:
//   K0: reorder weight (o,i,ab) -> g_W[ab][i][o]
//   K1: input transform x -> g_V[ab][i][t]     (t = n*1024 + p*32 + q)
//   K2: 36 batched GEMMs M[ab][o][t] = sum_i W[ab][i][o] * V[ab][i][t]
//   K3: output transform AT*M*AT^T + bias -> y

#define NT 32
#define TQ 16384           // N * nt * nt
#define CH 64
#define ABN 36
#define VSLICE (CH * TQ)   // 1,048,576 elements per ab

__device__ float g_V[ABN * CH * TQ];   // ~151 MB scratch
__device__ float g_M[ABN * CH * TQ];   // ~151 MB scratch
__device__ float g_W[ABN * CH * CH];   // 576 KB

// ---------------------------------------------------------------------------
// K0: weight reorder. src layout: w[o][i][ab] (o,i in 0..63, ab in 0..35)
// dst: g_W[ab][i][o]
// ---------------------------------------------------------------------------
__global__ void k_wreorder(const float* __restrict__ w) {
    int tid = blockIdx.x * blockDim.x + threadIdx.x;
    if (tid >= CH * CH * ABN) return;
    int ab = tid % ABN;
    int i  = (tid / ABN) % CH;
    int o  = tid / (ABN * CH);
    g_W[ab * (CH * CH) + i * CH + o] = w[tid];
}

// ---------------------------------------------------------------------------
// K1: input transform. One thread per (n, c, p, q) tile.
// V[a][b] = sum_ij BT[a][i] * d[i][j] * BT[b][j]
// BT rows:
//   [ 4, 0,-5, 0, 1, 0]
//   [ 0,-4,-4, 1, 1, 0]
//   [ 0, 4,-4,-1, 1, 0]
//   [ 0,-2,-1, 2, 1, 0]
//   [ 0, 2,-1,-2, 1, 0]
//   [ 0, 4, 0,-5, 0, 1]
// ---------------------------------------------------------------------------
__device__ __forceinline__ void bt_apply(const float d0, const float d1,
                                         const float d2, const float d3,
                                         const float d4, const float d5,
                                         float* out /*6*/) {
    out[0] = 4.f * d0 - 5.f * d2 + d4;
    out[1] = -4.f * (d1 + d2) + d3 + d4;
    out[2] = 4.f * (d1 - d2) - d3 + d4;
    out[3] = -2.f * d1 - d2 + 2.f * d3 + d4;
    out[4] = 2.f * d1 - d2 - 2.f * d3 + d4;
    out[5] = 4.f * d1 - 5.f * d3 + d5;
}

__global__ __launch_bounds__(256)
void k_input_transform(const float* __restrict__ x) {
    int tid = blockIdx.x * blockDim.x + threadIdx.x;   // 1,048,576 threads
    int q = tid & 31;
    int p = (tid >> 5) & 31;
    int c = (tid >> 10) & 63;
    int n = tid >> 16;

    const float* xp = x + (((long)n * CH + c) << 14);  // H*W = 16384
    int r0 = p * 4 - 1;
    int c0 = q * 4 - 1;

    float d[6][6];
#pragma unroll
    for (int i = 0; i < 6; i++) {
        int r = r0 + i;
        bool rv = (r >= 0) && (r < 128);
        const float* row = xp + r * 128;
#pragma unroll
        for (int j = 0; j < 6; j++) {
            int cc = c0 + j;
            d[i][j] = (rv && cc >= 0 && cc < 128) ? row[cc] : 0.f;
        }
    }

    // stage 1: over i (rows): w[a][j]
    float wrow[6][6];
#pragma unroll
    for (int j = 0; j < 6; j++) {
        float t[6];
        bt_apply(d[0][j], d[1][j], d[2][j], d[3][j], d[4][j], d[5][j], t);
#pragma unroll
        for (int a = 0; a < 6; a++) wrow[a][j] = t[a];
    }

    int t = (n << 10) + (p << 5) + q;
    long base = (long)c * TQ + t;
    // stage 2: over j (cols): V[a][b]
#pragma unroll
    for (int a = 0; a < 6; a++) {
        float v[6];
        bt_apply(wrow[a][0], wrow[a][1], wrow[a][2], wrow[a][3], wrow[a][4],
                 wrow[a][5], v);
#pragma unroll
        for (int b = 0; b < 6; b++) {
            g_V[(long)(a * 6 + b) * VSLICE + base] = v[b];
        }
    }
}

// ---------------------------------------------------------------------------
// K2: batched GEMM. grid = (TQ/128, 36). block = 256.
// CTA computes M[ab][0..64][tb..tb+128].
// smem: Ws[i][o] 16KB, Vs[i][t] 32KB. micro-tile 8(o) x 4(t) per thread.
// ---------------------------------------------------------------------------
__global__ __launch_bounds__(256)
void k_gemm() {
    __shared__ float Ws[64][64];    // [i][o]
    __shared__ float Vs[64][128];   // [i][t]

    int ab = blockIdx.y;
    int tb = blockIdx.x * 128;
    int tid = threadIdx.x;

    // load W slice: 4096 floats = 1024 float4
    {
        const float4* src = (const float4*)(g_W + (long)ab * (CH * CH));
        float4* dst = (float4*)&Ws[0][0];
#pragma unroll
        for (int r = 0; r < 4; r++) dst[tid + 256 * r] = src[tid + 256 * r];
    }
    // load V slice: 64 rows x 128 floats = 2048 float4
    {
        const float* src = g_V + (long)ab * VSLICE + tb;
#pragma unroll
        for (int it = 0; it < 8; it++) {
            int idx = tid + it * 256;
            int row = idx >> 5;
            int col = idx & 31;
            ((float4*)&Vs[row][0])[col] =
                ((const float4*)(src + (long)row * TQ))[col];
        }
    }
    __syncthreads();

    int tx = tid & 31;      // t group (4 cols)
    int ty = tid >> 5;      // o group (8 rows)

    float acc[8][4] = {};
#pragma unroll
    for (int k = 0; k < 64; k++) {
        float4 b = ((float4*)&Vs[k][0])[tx];
        float a[8];
#pragma unroll
        for (int r = 0; r < 8; r++) a[r] = Ws[k][ty * 8 + r];
#pragma unroll
        for (int r = 0; r < 8; r++) {
            acc[r][0] += a[r] * b.x;
            acc[r][1] += a[r] * b.y;
            acc[r][2] += a[r] * b.z;
            acc[r][3] += a[r] * b.w;
        }
    }

    float* mdst = g_M + (long)ab * VSLICE + tb;
#pragma unroll
    for (int r = 0; r < 8; r++) {
        int o = ty * 8 + r;
        ((float4*)(mdst + (long)o * TQ))[tx] =
            make_float4(acc[r][0], acc[r][1], acc[r][2], acc[r][3]);
    }
}

// ---------------------------------------------------------------------------
// K3: output transform + bias. One thread per (n, o, p, q).
// AT rows:
//   [1, 1, 1, 1, 1, 0]
//   [0, 1,-1, 2,-2, 0]
//   [0, 1, 1, 4, 4, 0]
//   [0, 1,-1, 8,-8, 1]
// ---------------------------------------------------------------------------
__global__ __launch_bounds__(256)
void k_output_transform(const float* __restrict__ bias,
                        float* __restrict__ y) {
    int tid = blockIdx.x * blockDim.x + threadIdx.x;   // 1,048,576
    int q = tid & 31;
    int p = (tid >> 5) & 31;
    int o = (tid >> 10) & 63;
    int n = tid >> 16;

    int t = (n << 10) + (p << 5) + q;
    long base = (long)o * TQ + t;

    float m[6][6];
#pragma unroll
    for (int a = 0; a < 6; a++)
#pragma unroll
        for (int b = 0; b < 6; b++)
            m[a][b] = g_M[(long)(a * 6 + b) * VSLICE + base];

    // stage 1: over a -> u[x][b]
    float u[4][6];
#pragma unroll
    for (int b = 0; b < 6; b++) {
        float m0 = m[0][b], m1 = m[1][b], m2 = m[2][b];
        float m3 = m[3][b], m4 = m[4][b], m5 = m[5][b];
        u[0][b] = m0 + m1 + m2 + m3 + m4;
        u[1][b] = m1 - m2 + 2.f * (m3 - m4);
        u[2][b] = m1 + m2 + 4.f * (m3 + m4);
        u[3][b] = m1 - m2 + 8.f * (m3 - m4) + m5;
    }

    float bv = bias[o];
    float* yp = y + (((long)n * CH + o) << 14) + (p * 4) * 128 + q * 4;
#pragma unroll
    for (int xr = 0; xr < 4; xr++) {
        float m0 = u[xr][0], m1 = u[xr][1], m2 = u[xr][2];
        float m3 = u[xr][3], m4 = u[xr][4], m5 = u[xr][5];
        float y0 = m0 + m1 + m2 + m3 + m4 + bv;
        float y1 = m1 - m2 + 2.f * (m3 - m4) + bv;
        float y2 = m1 + m2 + 4.f * (m3 + m4) + bv;
        float y3 = m1 - m2 + 8.f * (m3 - m4) + m5 + bv;
        ((float4*)(yp + xr * 128))[0] = make_float4(y0, y1, y2, y3);
    }
}

// ---------------------------------------------------------------------------
extern "C" void kernel_launch(void* const* d_in, const int* in_sizes, int n_in,
                              void* d_out, int out_size) {
    const float* x    = (const float*)d_in[0];   // (16,64,128,128)
    const float* w    = (const float*)d_in[1];   // (64,64,6,6)
    const float* bias = (const float*)d_in[2];   // (64,)
    float* y = (float*)d_out;                    // (16,64,128,128)

    k_wreorder<<<(CH * CH * ABN + 255) / 256, 256>>>(w);
    k_input_transform<<<4096, 256>>>(x);
    dim3 g2(TQ / 128, ABN);
    k_gemm<<<g2, 256>>>();
    k_output_transform<<<4096, 256>>>(bias, y);
}

// round 3
// speedup vs baseline: 1.7291x; 1.7291x over previous
#include <cuda_runtime.h>
#include <cuda_fp16.h>
#include <cstdint>

// Winograd F(4x4,3x3): N=16, Cin=Cout=64, H=W=128, pad=1, nt=32, T=16384.
// fp16 intermediates + mma.sync (HMMA) GEMM with fp32 accumulation.
// NOTE: harness compiles for plain sm_103 (no 'a'), so tcgen05 is unavailable;
// mma.sync.m16n8k16 is the baseline-feature tensor-core path.
//
//   K0: weight (o,i,ab) fp32 -> g_Wh[ab][o][i] fp16
//   K1: input transform x -> g_Vh[ab][i][t] fp16   (t = n*1024 + p*32 + q)
//   K2: HMMA: M[ab][o][t] = sum_i W[o][i] * V[i][t] -> g_Mh fp16
//   K3: output transform AT*M*AT^T + bias -> y fp32

#define TQ 16384
#define CH 64
#define ABN 36
#define VSLICE (CH * TQ)

__device__ __half g_Vh[ABN * CH * TQ];   // 75.5 MB
__device__ __half g_Mh[ABN * CH * TQ];   // 75.5 MB
__device__ __half g_Wh[ABN * CH * CH];

__device__ __forceinline__ uint32_t smem_u32(const void* p) {
    uint32_t a;
    asm("{ .reg .u64 t; cvta.to.shared.u64 t, %1; cvt.u32.u64 %0, t; }"
        : "=r"(a) : "l"(p));
    return a;
}

// ---------------------------------------------------------------------------
// K0: weight reorder. src w[o][i][ab] fp32 -> g_Wh[ab][o][i] fp16
// ---------------------------------------------------------------------------
__global__ void k_wreorder(const float* __restrict__ w) {
    int tid = blockIdx.x * blockDim.x + threadIdx.x;
    if (tid >= ABN * CH * CH) return;
    int i  = tid & 63;
    int o  = (tid >> 6) & 63;
    int ab = tid >> 12;
    g_Wh[tid] = __float2half_rn(w[(o * 64 + i) * ABN + ab]);
}

// ---------------------------------------------------------------------------
// K1: input transform -> g_Vh[ab][c][t] fp16
// ---------------------------------------------------------------------------
__device__ __forceinline__ void bt_apply(const float d0, const float d1,
                                         const float d2, const float d3,
                                         const float d4, const float d5,
                                         float* out) {
    out[0] = 4.f * d0 - 5.f * d2 + d4;
    out[1] = -4.f * (d1 + d2) + d3 + d4;
    out[2] = 4.f * (d1 - d2) - d3 + d4;
    out[3] = -2.f * d1 - d2 + 2.f * d3 + d4;
    out[4] = 2.f * d1 - d2 - 2.f * d3 + d4;
    out[5] = 4.f * d1 - 5.f * d3 + d5;
}

__global__ __launch_bounds__(256)
void k_input_transform(const float* __restrict__ x) {
    int tid = blockIdx.x * blockDim.x + threadIdx.x;
    int q = tid & 31;
    int p = (tid >> 5) & 31;
    int c = (tid >> 10) & 63;
    int n = tid >> 16;

    const float* xp = x + (((long)n * CH + c) << 14);
    int r0 = p * 4 - 1;
    int c0 = q * 4 - 1;

    float d[6][6];
#pragma unroll
    for (int i = 0; i < 6; i++) {
        int r = r0 + i;
        bool rv = (r >= 0) && (r < 128);
        const float* row = xp + r * 128;
#pragma unroll
        for (int j = 0; j < 6; j++) {
            int cc = c0 + j;
            d[i][j] = (rv && cc >= 0 && cc < 128) ? row[cc] : 0.f;
        }
    }

    float wrow[6][6];
#pragma unroll
    for (int j = 0; j < 6; j++) {
        float t[6];
        bt_apply(d[0][j], d[1][j], d[2][j], d[3][j], d[4][j], d[5][j], t);
#pragma unroll
        for (int a = 0; a < 6; a++) wrow[a][j] = t[a];
    }

    int t = (n << 10) + (p << 5) + q;
    int base = c * TQ + t;
#pragma unroll
    for (int a = 0; a < 6; a++) {
        float v[6];
        bt_apply(wrow[a][0], wrow[a][1], wrow[a][2], wrow[a][3], wrow[a][4],
                 wrow[a][5], v);
#pragma unroll
        for (int b = 0; b < 6; b++) {
            g_Vh[(a * 6 + b) * VSLICE + base] = __float2half_rn(v[b]);
        }
    }
}

// ---------------------------------------------------------------------------
// K2: HMMA GEMM. grid = (TQ/256, 36), block = 256 (8 warps).
// CTA tile: o=64, t=256, K=64 (resident).
// Warp tile: 32(o) x 64(t): 2 m16 x 8 n8 mma fragments, 4 k16 steps.
// A = W[o][i] (row-major m x k), B = V[i][t] (k x n, ldmatrix.trans).
// ---------------------------------------------------------------------------
__global__ __launch_bounds__(256, 2)
void k_gemm_hmma() {
    __shared__ __half Ws[64][72];    // [o][i], +8 pad
    __shared__ __half Vs[64][264];   // [i][t], +8 pad

    const int tid = threadIdx.x;
    const int wid = tid >> 5;
    const int lid = tid & 31;
    const int ab = blockIdx.y;
    const int tb = blockIdx.x * 256;

    // Load W tile: 64x64 fp16 = 512 uint4.
    {
        const uint4* Wp = (const uint4*)(g_Wh + ab * (CH * CH));
#pragma unroll
        for (int it = 0; it < 2; it++) {
            int idx = tid + it * 256;
            int r = idx >> 3, c = idx & 7;
            *(uint4*)&Ws[r][c * 8] = Wp[idx];
        }
    }
    // Load V tile: 64 rows x 256 t fp16 = 2048 uint4.
    {
        const __half* Vp = g_Vh + ab * VSLICE + tb;
#pragma unroll
        for (int it = 0; it < 8; it++) {
            int idx = tid + it * 256;
            int r = idx >> 5, c = idx & 31;
            *(uint4*)&Vs[r][c * 8] =
                *(const uint4*)(Vp + (size_t)r * TQ + c * 8);
        }
    }
    __syncthreads();

    const int o0  = (wid & 1) * 32;
    const int t0w = (wid >> 1) * 64;

    float acc[2][8][4];
#pragma unroll
    for (int mi = 0; mi < 2; mi++)
#pragma unroll
        for (int nj = 0; nj < 8; nj++)
#pragma unroll
            for (int r = 0; r < 4; r++) acc[mi][nj][r] = 0.f;

#pragma unroll
    for (int ks = 0; ks < 4; ks++) {
        const int k0 = ks * 16;

        // A fragments: 2 x ldmatrix.x4 (m16k16 each)
        uint32_t ra[2][4];
#pragma unroll
        for (int mi = 0; mi < 2; mi++) {
            int row = o0 + mi * 16 + (lid & 7) + ((lid >> 3) & 1) * 8;
            int col = k0 + (lid >> 4) * 8;
            uint32_t addr = smem_u32(&Ws[row][col]);
            asm volatile(
                "ldmatrix.sync.aligned.m8n8.x4.shared.b16 {%0,%1,%2,%3}, [%4];"
                : "=r"(ra[mi][0]), "=r"(ra[mi][1]), "=r"(ra[mi][2]),
                  "=r"(ra[mi][3])
                : "r"(addr));
        }
        // B fragments: 4 x ldmatrix.x4.trans (k16 x n16 each -> 2 n8 frags)
        uint32_t rb[8][2];
#pragma unroll
        for (int njp = 0; njp < 4; njp++) {
            int row = k0 + (lid & 7) + ((lid >> 3) & 1) * 8;
            int col = t0w + njp * 16 + (lid >> 4) * 8;
            uint32_t addr = smem_u32(&Vs[row][col]);
            uint32_t r0, r1, r2, r3;
            asm volatile(
                "ldmatrix.sync.aligned.m8n8.x4.trans.shared.b16 {%0,%1,%2,%3}, [%4];"
                : "=r"(r0), "=r"(r1), "=r"(r2), "=r"(r3)
                : "r"(addr));
            rb[njp * 2][0] = r0; rb[njp * 2][1] = r1;
            rb[njp * 2 + 1][0] = r2; rb[njp * 2 + 1][1] = r3;
        }

#pragma unroll
        for (int mi = 0; mi < 2; mi++)
#pragma unroll
            for (int nj = 0; nj < 8; nj++) {
                asm volatile(
                    "mma.sync.aligned.m16n8k16.row.col.f32.f16.f16.f32 "
                    "{%0,%1,%2,%3}, {%4,%5,%6,%7}, {%8,%9}, {%0,%1,%2,%3};"
                    : "+f"(acc[mi][nj][0]), "+f"(acc[mi][nj][1]),
                      "+f"(acc[mi][nj][2]), "+f"(acc[mi][nj][3])
                    : "r"(ra[mi][0]), "r"(ra[mi][1]), "r"(ra[mi][2]),
                      "r"(ra[mi][3]), "r"(rb[nj][0]), "r"(rb[nj][1]));
            }
    }

    // Epilogue: write fp16 M[ab][o][t] directly (half2 per c-pair).
    __half* Mp = g_Mh + ab * VSLICE;
#pragma unroll
    for (int mi = 0; mi < 2; mi++) {
        int orow = o0 + mi * 16 + (lid >> 2);
#pragma unroll
        for (int nj = 0; nj < 8; nj++) {
            int t = tb + t0w + nj * 8 + (lid & 3) * 2;
            *(__half2*)(Mp + orow * TQ + t) =
                __floats2half2_rn(acc[mi][nj][0], acc[mi][nj][1]);
            *(__half2*)(Mp + (orow + 8) * TQ + t) =
                __floats2half2_rn(acc[mi][nj][2], acc[mi][nj][3]);
        }
    }
}

// ---------------------------------------------------------------------------
// K3: output transform + bias (fp32 math, fp16 M reads).
// ---------------------------------------------------------------------------
__global__ __launch_bounds__(256)
void k_output_transform(const float* __restrict__ bias,
                        float* __restrict__ y) {
    int tid = blockIdx.x * blockDim.x + threadIdx.x;
    int q = tid & 31;
    int p = (tid >> 5) & 31;
    int o = (tid >> 10) & 63;
    int n = tid >> 16;

    int t = (n << 10) + (p << 5) + q;
    int base = o * TQ + t;

    float m[6][6];
#pragma unroll
    for (int a = 0; a < 6; a++)
#pragma unroll
        for (int b = 0; b < 6; b++)
            m[a][b] = __half2float(g_Mh[(a * 6 + b) * VSLICE + base]);

    float u[4][6];
#pragma unroll
    for (int b = 0; b < 6; b++) {
        float m0 = m[0][b], m1 = m[1][b], m2 = m[2][b];
        float m3 = m[3][b], m4 = m[4][b], m5 = m[5][b];
        u[0][b] = m0 + m1 + m2 + m3 + m4;
        u[1][b] = m1 - m2 + 2.f * (m3 - m4);
        u[2][b] = m1 + m2 + 4.f * (m3 + m4);
        u[3][b] = m1 - m2 + 8.f * (m3 - m4) + m5;
    }

    float bv = bias[o];
    float* yp = y + (((long)n * CH + o) << 14) + (p * 4) * 128 + q * 4;
#pragma unroll
    for (int xr = 0; xr < 4; xr++) {
        float m0 = u[xr][0], m1 = u[xr][1], m2 = u[xr][2];
        float m3 = u[xr][3], m4 = u[xr][4], m5 = u[xr][5];
        float y0 = m0 + m1 + m2 + m3 + m4 + bv;
        float y1 = m1 - m2 + 2.f * (m3 - m4) + bv;
        float y2 = m1 + m2 + 4.f * (m3 + m4) + bv;
        float y3 = m1 - m2 + 8.f * (m3 - m4) + m5 + bv;
        ((float4*)(yp + xr * 128))[0] = make_float4(y0, y1, y2, y3);
    }
}

// ---------------------------------------------------------------------------
extern "C" void kernel_launch(void* const* d_in, const int* in_sizes, int n_in,
                              void* d_out, int out_size) {
    const float* x    = (const float*)d_in[0];
    const float* w    = (const float*)d_in[1];
    const float* bias = (const float*)d_in[2];
    float* y = (float*)d_out;

    k_wreorder<<<(ABN * CH * CH + 255) / 256, 256>>>(w);
    k_input_transform<<<4096, 256>>>(x);
    dim3 g2(TQ / 256, ABN);
    k_gemm_hmma<<<g2, 256>>>();
    k_output_transform<<<4096, 256>>>(bias, y);
}